// round 12
// baseline (speedup 1.0000x reference)
#include <cuda_runtime.h>
#include <cuda_bf16.h>
#include <stdint.h>
#include <math.h>

// Problem constants
#define HDIM 128
#define FDIM 64
#define THDIM 384              // 3*H
#define IS3  0.5773502691896258f      // 1/sqrt(3)
#define ISH  0.08838834764831845f     // 1/sqrt(128)
#define SSC  1.6666666666666667f      // 1/0.6

#define MAXN 50000
#define MAXE 400000
#define CHUNK 16384            // edges per chunk: 25MB rbf slice, L2-resident

typedef unsigned long long ull;
typedef unsigned int u32;

// Scratch (device globals: allocation-free)
__device__ float g_xd  [MAXN * THDIM];
__device__ float g_h1  [MAXN * FDIM];
__device__ float g_xh  [MAXN * THDIM];
__device__ float g_lvec[MAXN * 3 * HDIM];
__device__ float g_rbf [CHUNK * THDIM];          // per-chunk rbf+bias (reused)
__device__ __nv_bfloat16 g_efh[(size_t)MAXE * FDIM];  // sorted efeat hi
__device__ __nv_bfloat16 g_efm[(size_t)MAXE * FDIM];  // sorted efeat mid
__device__ __nv_bfloat16 g_efl[(size_t)MAXE * FDIM];  // sorted efeat lo
__device__ __nv_bfloat16 g_wth[THDIM * FDIM];    // We^T hi  [384][64]
__device__ __nv_bfloat16 g_wtm[THDIM * FDIM];    // We^T mid
__device__ __nv_bfloat16 g_wtl[THDIM * FDIM];    // We^T lo
__device__ float g_evs [MAXE * 3];               // edge_vector sorted
__device__ int   g_deg [MAXN];
__device__ int   g_cur [MAXN];
__device__ int   g_bsum[256];
__device__ int   g_boff[256];
__device__ int   g_elist[MAXE];
__device__ int   g_js  [MAXE];
__device__ int   g_is  [MAXE];

// ---------------------------------------------------------------------------
// Packed fp32x2 helpers (FFMA2)
// ---------------------------------------------------------------------------
__device__ __forceinline__ ull pk(float lo, float hi) {
    ull r; asm("mov.b64 %0, {%1, %2};" : "=l"(r) : "f"(lo), "f"(hi)); return r;
}
__device__ __forceinline__ void upk(ull v, float& lo, float& hi) {
    asm("mov.b64 {%0, %1}, %2;" : "=f"(lo), "=f"(hi) : "l"(v));
}
__device__ __forceinline__ void fma2(ull& d, ull a, ull b) {
    asm("fma.rn.f32x2 %0, %1, %2, %0;" : "+l"(d) : "l"(a), "l"(b));
}

// 3-way bf16 split: x = h + m + l, residual ~2^-27 |x|
__device__ __forceinline__ void split3_bf(float x, __nv_bfloat16& h,
                                          __nv_bfloat16& m, __nv_bfloat16& l) {
    h = __float2bfloat16(x);
    float hf = __bfloat162float(h);
    m = __float2bfloat16(x - hf);
    float mf = __bfloat162float(m);
    l = __float2bfloat16(x - hf - mf);
}

// m16n8k16 bf16 mma (sm_80+ standard feature; verified compiles on compute_103)
__device__ __forceinline__ void mma_bf16(float* d, const u32* a, u32 b0, u32 b1) {
    asm volatile(
        "mma.sync.aligned.m16n8k16.row.col.f32.bf16.bf16.f32 "
        "{%0,%1,%2,%3}, {%4,%5,%6,%7}, {%8,%9}, {%0,%1,%2,%3};"
        : "+f"(d[0]), "+f"(d[1]), "+f"(d[2]), "+f"(d[3])
        : "r"(a[0]), "r"(a[1]), "r"(a[2]), "r"(a[3]), "r"(b0), "r"(b1));
}

// ---------------------------------------------------------------------------
// Utility + CSR build (counting sort by source j)
// ---------------------------------------------------------------------------
__global__ void zero_kernel(float4* __restrict__ p, long n4) {
    long i = (long)blockIdx.x * blockDim.x + threadIdx.x;
    if (i < n4) p[i] = make_float4(0.f, 0.f, 0.f, 0.f);
}
__global__ void zeroi_kernel(int* __restrict__ p, int n) {
    int i = blockIdx.x * blockDim.x + threadIdx.x;
    if (i < n) p[i] = 0;
}
__global__ void hist_kernel(const int* __restrict__ key, int* __restrict__ deg, int E) {
    int e = blockIdx.x * blockDim.x + threadIdx.x;
    if (e < E) atomicAdd(&deg[key[e]], 1);
}
__global__ void scan1_kernel(const int* __restrict__ deg, int* __restrict__ bsum, int Nn) {
    __shared__ int s[256];
    int t = threadIdx.x;
    int idx = blockIdx.x * 256 + t;
    s[t] = (idx < Nn) ? deg[idx] : 0;
    __syncthreads();
#pragma unroll
    for (int d = 128; d > 0; d >>= 1) {
        if (t < d) s[t] += s[t + d];
        __syncthreads();
    }
    if (t == 0) bsum[blockIdx.x] = s[0];
}
__global__ void scan2_kernel(const int* __restrict__ bsum, int* __restrict__ boff, int nb) {
    __shared__ int s[256];
    int t = threadIdx.x;
    s[t] = (t < nb) ? bsum[t] : 0;
    __syncthreads();
#pragma unroll
    for (int d = 1; d < 256; d <<= 1) {
        int v = (t >= d) ? s[t - d] : 0;
        __syncthreads();
        s[t] += v;
        __syncthreads();
    }
    if (t < nb) boff[t] = (t == 0) ? 0 : s[t - 1];
}
__global__ void scan3_kernel(const int* __restrict__ deg, const int* __restrict__ boff,
                             int* __restrict__ cur, int Nn) {
    __shared__ int s[256];
    int t = threadIdx.x;
    int idx = blockIdx.x * 256 + t;
    int v = (idx < Nn) ? deg[idx] : 0;
    s[t] = v;
    __syncthreads();
#pragma unroll
    for (int d = 1; d < 256; d <<= 1) {
        int x = (t >= d) ? s[t - d] : 0;
        __syncthreads();
        s[t] += x;
        __syncthreads();
    }
    if (idx < Nn)
        cur[idx] = boff[blockIdx.x] + s[t] - v;
}
__global__ void fill_kernel(const int* __restrict__ ej, const int* __restrict__ ei,
                            const float* __restrict__ ev,
                            int* __restrict__ cursor, int* __restrict__ elist,
                            int* __restrict__ js, int* __restrict__ is,
                            float* __restrict__ evs, int E) {
    int e = blockIdx.x * blockDim.x + threadIdx.x;
    if (e < E) {
        int j = ej[e];
        int slot = atomicAdd(&cursor[j], 1);
        elist[slot] = e;
        js[slot] = j;
        is[slot] = ei[e];
        evs[slot * 3 + 0] = ev[(size_t)e * 3 + 0];
        evs[slot * 3 + 1] = ev[(size_t)e * 3 + 1];
        evs[slot * 3 + 2] = ev[(size_t)e * 3 + 2];
    }
}
// gather efeat into sorted order AND split 3-way to bf16
__global__ void gather_split_kernel(const float* __restrict__ efeat,
                                    const int* __restrict__ elist,
                                    __nv_bfloat16* __restrict__ efh,
                                    __nv_bfloat16* __restrict__ efm,
                                    __nv_bfloat16* __restrict__ efl, int E) {
    long idx = (long)blockIdx.x * blockDim.x + threadIdx.x;   // E*64
    if (idx < (long)E * FDIM) {
        int slot = (int)(idx >> 6);
        int k = (int)(idx & 63);
        int e = elist[slot];
        float v = efeat[(size_t)e * FDIM + k];
        __nv_bfloat16 h, m, l;
        split3_bf(v, h, m, l);
        efh[idx] = h;
        efm[idx] = m;
        efl[idx] = l;
    }
}
// We^T hi/mid/lo: wt[n][k] = We[k][n]
__global__ void prep_w_kernel(const float* __restrict__ We,
                              __nv_bfloat16* __restrict__ wth,
                              __nv_bfloat16* __restrict__ wtm,
                              __nv_bfloat16* __restrict__ wtl) {
    int idx = blockIdx.x * 256 + threadIdx.x;
    if (idx < THDIM * FDIM) {
        int n = idx >> 6, k = idx & 63;
        float v = We[(size_t)k * THDIM + n];
        __nv_bfloat16 h, m, l;
        split3_bf(v, h, m, l);
        wth[idx] = h;
        wtm[idx] = m;
        wtl[idx] = l;
    }
}

// ---------------------------------------------------------------------------
// fp32 SGEMM with FFMA2 inner product: C = act(A @ W + bias)
// ---------------------------------------------------------------------------
template<int BM, int BN, int BK, int TM, int TN, int ACT, int HASB>
__global__ void __launch_bounds__(256)
sgemm_kernel(const float* __restrict__ A, const float* __restrict__ W,
             const float* __restrict__ bias, float* __restrict__ C,
             int M, int N, int K)
{
    __shared__ float As[BK][BM];
    __shared__ float Ws[BK][BN];

    const int tid  = threadIdx.x;
    const int row0 = blockIdx.x * BM;
    const int col0 = blockIdx.y * BN;
    const int tx   = tid % (BN / TN);
    const int ty   = tid / (BN / TN);

    const int aRow = tid / (BK / 4);
    const int aCol = (tid % (BK / 4)) * 4;
    const int wRow = tid / (BN / 4);
    const int wCol = (tid % (BN / 4)) * 4;

    ull acc2[TM][TN / 2];
#pragma unroll
    for (int i = 0; i < TM; i++)
#pragma unroll
        for (int j = 0; j < TN / 2; j++) acc2[i][j] = 0ULL;

    for (int k0 = 0; k0 < K; k0 += BK) {
#pragma unroll
        for (int r = 0; r < BM; r += 256 / (BK / 4)) {
            int gr = row0 + aRow + r;
            float4 v = make_float4(0.f, 0.f, 0.f, 0.f);
            if (gr < M)
                v = *(const float4*)(A + (size_t)gr * K + k0 + aCol);
            As[aCol + 0][aRow + r] = v.x;
            As[aCol + 1][aRow + r] = v.y;
            As[aCol + 2][aRow + r] = v.z;
            As[aCol + 3][aRow + r] = v.w;
        }
#pragma unroll
        for (int r = 0; r < BK; r += 256 / (BN / 4)) {
            *(float4*)&Ws[wRow + r][wCol] =
                *(const float4*)(W + (size_t)(k0 + wRow + r) * N + col0 + wCol);
        }
        __syncthreads();

#pragma unroll
        for (int k = 0; k < BK; k++) {
            float am[TM], wn[TN];
#pragma unroll
            for (int i = 0; i < TM; i += 4)
                *(float4*)&am[i] = *(const float4*)&As[k][ty * TM + i];
#pragma unroll
            for (int j = 0; j < TN; j += 4)
                *(float4*)&wn[j] = *(const float4*)&Ws[k][tx * TN + j];
            ull wn2[TN / 2];
#pragma unroll
            for (int j = 0; j < TN / 2; j++) wn2[j] = pk(wn[2 * j], wn[2 * j + 1]);
#pragma unroll
            for (int i = 0; i < TM; i++) {
                ull a2 = pk(am[i], am[i]);
#pragma unroll
                for (int j = 0; j < TN / 2; j++)
                    fma2(acc2[i][j], a2, wn2[j]);
            }
        }
        __syncthreads();
    }

    float bv[TN];
#pragma unroll
    for (int j = 0; j < TN; j++)
        bv[j] = HASB ? bias[col0 + tx * TN + j] : 0.f;

#pragma unroll
    for (int i = 0; i < TM; i++) {
        int gr = row0 + ty * TM + i;
        if (gr >= M) continue;
#pragma unroll
        for (int j = 0; j < TN; j += 4) {
            float t[4];
            upk(acc2[i][j / 2],     t[0], t[1]);
            upk(acc2[i][j / 2 + 1], t[2], t[3]);
#pragma unroll
            for (int q = 0; q < 4; q++) {
                float v = t[q] + bv[j + q];
                if (ACT == 1) v = v / (1.f + expf(-v)) * SSC;  // ScaledSiLU
                t[q] = v;
            }
            *(float4*)(C + (size_t)gr * N + col0 + tx * TN + j) =
                make_float4(t[0], t[1], t[2], t[3]);
        }
    }
}

// ---------------------------------------------------------------------------
// rbf HMMA kernel: rbf[chunk] = efs @ We + be  (3-way split bf16, 6 terms:
// hh + hm + mh + mm + hl + lh -> residual ~2^-27, fp32-level accuracy)
// CTA tile: 64 edges x 384 cols. 8 warps: 2 M-tiles(32) x 4 N-quarters(96).
// ---------------------------------------------------------------------------
__global__ void __launch_bounds__(256)
rbf_mma_kernel(const __nv_bfloat16* __restrict__ efh,
               const __nv_bfloat16* __restrict__ efm,
               const __nv_bfloat16* __restrict__ efl,
               const __nv_bfloat16* __restrict__ wth,
               const __nv_bfloat16* __restrict__ wtm,
               const __nv_bfloat16* __restrict__ wtl,
               const float* __restrict__ be,
               float* __restrict__ rbf, int c0, int ntiles)
{
    const int w    = threadIdx.x >> 5;
    const int lane = threadIdx.x & 31;
    const int g    = lane >> 2;
    const int t    = lane & 3;
    const int mt   = w >> 2;          // 0..1
    const int nq   = w & 3;           // 0..3

    for (int tile = blockIdx.x; tile < ntiles; tile += gridDim.x) {
        const int mrow = tile * 64 + mt * 32;         // chunk-local row base
        const long slot0 = (long)c0 + mrow;           // global sorted slot

        float acc[2][12][4];
#pragma unroll
        for (int mi = 0; mi < 2; mi++)
#pragma unroll
            for (int nt = 0; nt < 12; nt++)
#pragma unroll
                for (int c = 0; c < 4; c++) acc[mi][nt][c] = 0.f;

#pragma unroll
        for (int ks = 0; ks < 4; ks++) {
            const int k0 = ks * 16;
            u32 ah[2][4], am[2][4], al[2][4];
#pragma unroll
            for (int mi = 0; mi < 2; mi++) {
                long r = slot0 + mi * 16;
                long o0 = (r + g) * FDIM + k0 + 2 * t;
                long o8 = (r + 8 + g) * FDIM + k0 + 2 * t;
                ah[mi][0] = *(const u32*)(efh + o0);
                ah[mi][1] = *(const u32*)(efh + o8);
                ah[mi][2] = *(const u32*)(efh + o0 + 8);
                ah[mi][3] = *(const u32*)(efh + o8 + 8);
                am[mi][0] = *(const u32*)(efm + o0);
                am[mi][1] = *(const u32*)(efm + o8);
                am[mi][2] = *(const u32*)(efm + o0 + 8);
                am[mi][3] = *(const u32*)(efm + o8 + 8);
                al[mi][0] = *(const u32*)(efl + o0);
                al[mi][1] = *(const u32*)(efl + o8);
                al[mi][2] = *(const u32*)(efl + o0 + 8);
                al[mi][3] = *(const u32*)(efl + o8 + 8);
            }
#pragma unroll
            for (int nt = 0; nt < 12; nt++) {
                int n = nq * 96 + nt * 8 + g;
                long ob = (long)n * FDIM + k0 + 2 * t;
                u32 bh0 = *(const u32*)(wth + ob);
                u32 bh1 = *(const u32*)(wth + ob + 8);
                u32 bm0 = *(const u32*)(wtm + ob);
                u32 bm1 = *(const u32*)(wtm + ob + 8);
                u32 bl0 = *(const u32*)(wtl + ob);
                u32 bl1 = *(const u32*)(wtl + ob + 8);
#pragma unroll
                for (int mi = 0; mi < 2; mi++) {
                    mma_bf16(acc[mi][nt], ah[mi], bh0, bh1);   // hh
                    mma_bf16(acc[mi][nt], ah[mi], bm0, bm1);   // hm
                    mma_bf16(acc[mi][nt], am[mi], bh0, bh1);   // mh
                    mma_bf16(acc[mi][nt], am[mi], bm0, bm1);   // mm
                    mma_bf16(acc[mi][nt], ah[mi], bl0, bl1);   // hl
                    mma_bf16(acc[mi][nt], al[mi], bh0, bh1);   // lh
                }
            }
        }

        // epilogue: add bias, store (chunk-local rows)
#pragma unroll
        for (int mi = 0; mi < 2; mi++) {
            int ra = mrow + mi * 16 + g;
#pragma unroll
            for (int nt = 0; nt < 12; nt++) {
                int c = nq * 96 + nt * 8 + 2 * t;
                float b0v = be[c], b1v = be[c + 1];
                *(float2*)(rbf + (size_t)ra * THDIM + c) =
                    make_float2(acc[mi][nt][0] + b0v, acc[mi][nt][1] + b1v);
                *(float2*)(rbf + (size_t)(ra + 8) * THDIM + c) =
                    make_float2(acc[mi][nt][2] + b0v, acc[mi][nt][3] + b1v);
            }
        }
    }
}

// ---------------------------------------------------------------------------
// Vectorized global reduction
// ---------------------------------------------------------------------------
__device__ __forceinline__ void red4(float* p, float4 v) {
    asm volatile("red.global.add.v4.f32 [%0], {%1,%2,%3,%4};"
                 :: "l"(p), "f"(v.x), "f"(v.y), "f"(v.z), "f"(v.w)
                 : "memory");
}

// ---------------------------------------------------------------------------
// Edge elementwise + scatter (j-sorted, bias already in rbf): 32 thr/edge.
// ---------------------------------------------------------------------------
__global__ void edge_kernel(const float* __restrict__ xh, const float* __restrict__ xd,
                            const float* __restrict__ vec, const float* __restrict__ rbf,
                            const float* __restrict__ evs,
                            const int* __restrict__ js, const int* __restrict__ is,
                            float* __restrict__ dx, float* __restrict__ dvec,
                            int c0, int cnt)
{
    long gth = (long)blockIdx.x * blockDim.x + threadIdx.x;
    int er = (int)(gth >> 5);
    int q  = (int)(gth & 31);
    if (er >= cnt) return;
    int es = c0 + er;

    int j = js[es];
    int i = is[es];

    const float4* xhj = (const float4*)(xh + (size_t)j * THDIM);
    const float4* xdj = (const float4*)(xd + (size_t)j * THDIM);
    const float4* xdi = (const float4*)(xd + (size_t)i * THDIM);
    const float4* rb  = (const float4*)(rbf + (size_t)er * THDIM);

    float4 m0, m1, m2;
    {
        float4 a = xhj[q], b1 = xdj[q], b2 = xdi[q], r = rb[q];
        m0.x = a.x * (b1.x + b2.x) * r.x * IS3;
        m0.y = a.y * (b1.y + b2.y) * r.y * IS3;
        m0.z = a.z * (b1.z + b2.z) * r.z * IS3;
        m0.w = a.w * (b1.w + b2.w) * r.w * IS3;
    }
    {
        float4 a = xhj[32 + q], b1 = xdj[32 + q], b2 = xdi[32 + q], r = rb[32 + q];
        m1.x = a.x * (b1.x + b2.x) * r.x * IS3;
        m1.y = a.y * (b1.y + b2.y) * r.y * IS3;
        m1.z = a.z * (b1.z + b2.z) * r.z * IS3;
        m1.w = a.w * (b1.w + b2.w) * r.w * IS3;
    }
    {
        float4 a = xhj[64 + q], b1 = xdj[64 + q], b2 = xdi[64 + q], r = rb[64 + q];
        m2.x = a.x * (b1.x + b2.x) * r.x * IS3;
        m2.y = a.y * (b1.y + b2.y) * r.y * IS3;
        m2.z = a.z * (b1.z + b2.z) * r.z * IS3;
        m2.w = a.w * (b1.w + b2.w) * r.w * IS3;
    }

    float evd0 = evs[(size_t)es * 3 + 0];
    float evd1 = evs[(size_t)es * 3 + 1];
    float evd2 = evs[(size_t)es * 3 + 2];

    const float4* vj = (const float4*)(vec + (size_t)j * THDIM);
    float* dvbase = dvec + (size_t)i * THDIM;
    int h0 = q * 4;

    float4 v0 = vj[q], v1 = vj[32 + q], v2 = vj[64 + q];
    float4 r0, r1, r2;
    r0.x = (m0.x * v0.x + m1.x * evd0) * ISH;
    r0.y = (m0.y * v0.y + m1.y * evd0) * ISH;
    r0.z = (m0.z * v0.z + m1.z * evd0) * ISH;
    r0.w = (m0.w * v0.w + m1.w * evd0) * ISH;
    r1.x = (m0.x * v1.x + m1.x * evd1) * ISH;
    r1.y = (m0.y * v1.y + m1.y * evd1) * ISH;
    r1.z = (m0.z * v1.z + m1.z * evd1) * ISH;
    r1.w = (m0.w * v1.w + m1.w * evd1) * ISH;
    r2.x = (m0.x * v2.x + m1.x * evd2) * ISH;
    r2.y = (m0.y * v2.y + m1.y * evd2) * ISH;
    r2.z = (m0.z * v2.z + m1.z * evd2) * ISH;
    r2.w = (m0.w * v2.w + m1.w * evd2) * ISH;

    red4(dvbase + h0, r0);
    red4(dvbase + HDIM + h0, r1);
    red4(dvbase + 2 * HDIM + h0, r2);
    red4(dx + (size_t)i * HDIM + h0, m2);
}

// ---------------------------------------------------------------------------
// Vector activation epilogue
// ---------------------------------------------------------------------------
__global__ void combine_kernel(const float* __restrict__ lvec,
                               const float* __restrict__ Wg,
                               float* __restrict__ dvec, int Nn)
{
    __shared__ float wg_s[HDIM];
    __shared__ float red_s[4][3];
    int t = threadIdx.x;   // 128
    wg_s[t] = Wg[t];
    __syncthreads();

    for (int n = blockIdx.x; n < Nn; n += gridDim.x) {
        const float* vr = dvec + (size_t)n * THDIM;
        float v0 = vr[t], v1 = vr[HDIM + t], v2 = vr[2 * HDIM + t];
        float w = wg_s[t];
        float p0 = v0 * w, p1 = v1 * w, p2 = v2 * w;
#pragma unroll
        for (int off = 16; off > 0; off >>= 1) {
            p0 += __shfl_xor_sync(0xffffffffu, p0, off);
            p1 += __shfl_xor_sync(0xffffffffu, p1, off);
            p2 += __shfl_xor_sync(0xffffffffu, p2, off);
        }
        if ((t & 31) == 0) {
            red_s[t >> 5][0] = p0;
            red_s[t >> 5][1] = p1;
            red_s[t >> 5][2] = p2;
        }
        __syncthreads();
        float gv0 = red_s[0][0] + red_s[1][0] + red_s[2][0] + red_s[3][0];
        float gv1 = red_s[0][1] + red_s[1][1] + red_s[2][1] + red_s[3][1];
        float gv2 = red_s[0][2] + red_s[1][2] + red_s[2][2] + red_s[3][2];

        const float* lv = lvec + (size_t)n * THDIM;
        float l0 = lv[t], l1 = lv[HDIM + t], l2 = lv[2 * HDIM + t];
        float dot = l0 * gv0 + l1 * gv1 + l2 * gv2;

        float* o = dvec + (size_t)n * THDIM;
        if (dot >= 0.f) {
            o[t] = l0; o[HDIM + t] = l1; o[2 * HDIM + t] = l2;
        } else {
            o[t]            = (l0 + gv0) * 0.5f;
            o[HDIM + t]     = (l1 + gv1) * 0.5f;
            o[2 * HDIM + t] = (l2 + gv2) * 0.5f;
        }
        __syncthreads();
    }
}

// ---------------------------------------------------------------------------
// Launch
// ---------------------------------------------------------------------------
extern "C" void kernel_launch(void* const* d_in, const int* in_sizes, int n_in,
                              void* d_out, int out_size)
{
    const float* x     = (const float*)d_in[0];
    const float* xdef  = (const float*)d_in[1];
    const float* vec   = (const float*)d_in[2];
    const float* efeat = (const float*)d_in[3];
    const float* evec  = (const float*)d_in[4];
    const int*   eidx  = (const int*)  d_in[5];
    const float* Wd    = (const float*)d_in[6];
    const float* bd    = (const float*)d_in[7];
    const float* W1    = (const float*)d_in[8];
    const float* b1    = (const float*)d_in[9];
    const float* W2    = (const float*)d_in[10];
    const float* b2    = (const float*)d_in[11];
    const float* We    = (const float*)d_in[12];
    const float* be    = (const float*)d_in[13];
    const float* Wl    = (const float*)d_in[14];
    const float* Wg    = (const float*)d_in[15];

    int N = in_sizes[0] / HDIM;     // 50000
    int E = in_sizes[4] / 3;        // 400000

    float *p_xd, *p_h1, *p_xh, *p_lvec, *p_rbf, *p_evs;
    __nv_bfloat16 *p_efh, *p_efm, *p_efl, *p_wth, *p_wtm, *p_wtl;
    int *p_deg, *p_cur, *p_bsum, *p_boff, *p_elist, *p_js, *p_is;
    cudaGetSymbolAddress((void**)&p_xd,    g_xd);
    cudaGetSymbolAddress((void**)&p_h1,    g_h1);
    cudaGetSymbolAddress((void**)&p_xh,    g_xh);
    cudaGetSymbolAddress((void**)&p_lvec,  g_lvec);
    cudaGetSymbolAddress((void**)&p_rbf,   g_rbf);
    cudaGetSymbolAddress((void**)&p_evs,   g_evs);
    cudaGetSymbolAddress((void**)&p_efh,   g_efh);
    cudaGetSymbolAddress((void**)&p_efm,   g_efm);
    cudaGetSymbolAddress((void**)&p_efl,   g_efl);
    cudaGetSymbolAddress((void**)&p_wth,   g_wth);
    cudaGetSymbolAddress((void**)&p_wtm,   g_wtm);
    cudaGetSymbolAddress((void**)&p_wtl,   g_wtl);
    cudaGetSymbolAddress((void**)&p_deg,   g_deg);
    cudaGetSymbolAddress((void**)&p_cur,   g_cur);
    cudaGetSymbolAddress((void**)&p_bsum,  g_bsum);
    cudaGetSymbolAddress((void**)&p_boff,  g_boff);
    cudaGetSymbolAddress((void**)&p_elist, g_elist);
    cudaGetSymbolAddress((void**)&p_js,    g_js);
    cudaGetSymbolAddress((void**)&p_is,    g_is);

    float* dx   = (float*)d_out;
    float* dvec = (float*)d_out + (size_t)N * HDIM;

    const int* ej = eidx;
    const int* ei = eidx + E;

    // 0) zero accumulators + CSR (sort by j) + prep bf16 operands
    long n4 = (long)out_size / 4;
    zero_kernel<<<(unsigned)((n4 + 255) / 256), 256>>>((float4*)d_out, n4);
    int nb = (N + 255) / 256;
    zeroi_kernel<<<(N + 255) / 256, 256>>>(p_deg, N);
    hist_kernel<<<(E + 255) / 256, 256>>>(ej, p_deg, E);
    scan1_kernel<<<nb, 256>>>(p_deg, p_bsum, N);
    scan2_kernel<<<1, 256>>>(p_bsum, p_boff, nb);
    scan3_kernel<<<nb, 256>>>(p_deg, p_boff, p_cur, N);
    fill_kernel<<<(E + 255) / 256, 256>>>(ej, ei, evec, p_cur, p_elist,
                                          p_js, p_is, p_evs, E);
    long ngs = (long)E * FDIM;
    gather_split_kernel<<<(unsigned)((ngs + 255) / 256), 256>>>(
        efeat, p_elist, p_efh, p_efm, p_efl, E);
    prep_w_kernel<<<(THDIM * FDIM + 255) / 256, 256>>>(We, p_wth, p_wtm, p_wtl);

    dim3 gN((N + 127) / 128, 3);
    dim3 gN1((N + 127) / 128, 1);
    dim3 gL((3 * N + 127) / 128, 1);

    // node-side GEMMs (fp32 FFMA2)
    sgemm_kernel<128,128,16,8,8,0,1><<<gN, 256>>>(xdef, Wd, bd, p_xd, N, THDIM, HDIM);
    sgemm_kernel<128, 64,16,8,4,1,1><<<gN1,256>>>(x, W1, b1, p_h1, N, FDIM, HDIM);
    sgemm_kernel<128,128,16,8,8,0,1><<<gN, 256>>>(p_h1, W2, b2, p_xh, N, THDIM, FDIM);

    // chunked: HMMA rbf GEMM -> L2-resident slice -> edge elementwise+scatter
    for (int c0 = 0; c0 < E; c0 += CHUNK) {
        int cnt = (E - c0 < CHUNK) ? (E - c0) : CHUNK;
        int tiles = cnt / 64;          // E and CHUNK are multiples of 64
        rbf_mma_kernel<<<tiles, 256>>>(p_efh, p_efm, p_efl,
                                       p_wth, p_wtm, p_wtl, be,
                                       p_rbf, c0, tiles);
        long tot = (long)cnt * 32;
        edge_kernel<<<(unsigned)((tot + 255) / 256), 256>>>(
            p_xh, p_xd, vec, p_rbf, p_evs, p_js, p_is, dx, dvec, c0, cnt);
    }

    // lvec = d_vec_raw @ W_lvec
    sgemm_kernel<128,128,16,8,8,0,0><<<gL, 256>>>(dvec, Wl, nullptr, p_lvec, 3 * N, HDIM, HDIM);

    // vector activation epilogue
    combine_kernel<<<2048, 128>>>(p_lvec, Wg, dvec, N);
}

// round 13
// speedup vs baseline: 2.3639x; 2.3639x over previous
#include <cuda_runtime.h>
#include <stdint.h>
#include <math.h>

// Problem constants
#define HDIM 128
#define FDIM 64
#define THDIM 384              // 3*H
#define IS3  0.5773502691896258f      // 1/sqrt(3)
#define ISH  0.08838834764831845f     // 1/sqrt(128)
#define SSC  1.6666666666666667f      // 1/0.6

#define MAXN 50000
#define MAXE 400000
#define EBA 8                  // edges per warp-group

typedef unsigned long long ull;

// Scratch (device globals: allocation-free)
__device__ float g_xd  [MAXN * THDIM];
__device__ float g_h1  [MAXN * FDIM];
__device__ float g_xh  [MAXN * THDIM];
__device__ float g_lvec[MAXN * 3 * HDIM];
__device__ int   g_deg [MAXN];
__device__ int   g_cur [MAXN];
__device__ int   g_bsum[256];
__device__ int   g_boff[256];
__device__ int   g_elist[MAXE];
__device__ int   g_js  [MAXE];
__device__ int   g_is  [MAXE];

// ---------------------------------------------------------------------------
// Packed fp32x2 helpers (FFMA2 — ptxas never auto-fuses)
// ---------------------------------------------------------------------------
__device__ __forceinline__ ull pk(float lo, float hi) {
    ull r; asm("mov.b64 %0, {%1, %2};" : "=l"(r) : "f"(lo), "f"(hi)); return r;
}
__device__ __forceinline__ void upk(ull v, float& lo, float& hi) {
    asm("mov.b64 {%0, %1}, %2;" : "=f"(lo), "=f"(hi) : "l"(v));
}
__device__ __forceinline__ void fma2(ull& d, ull a, ull b) {
    asm("fma.rn.f32x2 %0, %1, %2, %0;" : "+l"(d) : "l"(a), "l"(b));
}

// ---------------------------------------------------------------------------
// Utility + CSR build (counting sort by source j)
// ---------------------------------------------------------------------------
__global__ void zero_kernel(float4* __restrict__ p, long n4) {
    long i = (long)blockIdx.x * blockDim.x + threadIdx.x;
    if (i < n4) p[i] = make_float4(0.f, 0.f, 0.f, 0.f);
}
__global__ void zeroi_kernel(int* __restrict__ p, int n) {
    int i = blockIdx.x * blockDim.x + threadIdx.x;
    if (i < n) p[i] = 0;
}
__global__ void hist_kernel(const int* __restrict__ key, int* __restrict__ deg, int E) {
    int e = blockIdx.x * blockDim.x + threadIdx.x;
    if (e < E) atomicAdd(&deg[key[e]], 1);
}
__global__ void scan1_kernel(const int* __restrict__ deg, int* __restrict__ bsum, int Nn) {
    __shared__ int s[256];
    int t = threadIdx.x;
    int idx = blockIdx.x * 256 + t;
    s[t] = (idx < Nn) ? deg[idx] : 0;
    __syncthreads();
#pragma unroll
    for (int d = 128; d > 0; d >>= 1) {
        if (t < d) s[t] += s[t + d];
        __syncthreads();
    }
    if (t == 0) bsum[blockIdx.x] = s[0];
}
__global__ void scan2_kernel(const int* __restrict__ bsum, int* __restrict__ boff, int nb) {
    __shared__ int s[256];
    int t = threadIdx.x;
    s[t] = (t < nb) ? bsum[t] : 0;
    __syncthreads();
#pragma unroll
    for (int d = 1; d < 256; d <<= 1) {
        int v = (t >= d) ? s[t - d] : 0;
        __syncthreads();
        s[t] += v;
        __syncthreads();
    }
    if (t < nb) boff[t] = (t == 0) ? 0 : s[t - 1];
}
__global__ void scan3_kernel(const int* __restrict__ deg, const int* __restrict__ boff,
                             int* __restrict__ cur, int Nn) {
    __shared__ int s[256];
    int t = threadIdx.x;
    int idx = blockIdx.x * 256 + t;
    int v = (idx < Nn) ? deg[idx] : 0;
    s[t] = v;
    __syncthreads();
#pragma unroll
    for (int d = 1; d < 256; d <<= 1) {
        int x = (t >= d) ? s[t - d] : 0;
        __syncthreads();
        s[t] += x;
        __syncthreads();
    }
    if (idx < Nn)
        cur[idx] = boff[blockIdx.x] + s[t] - v;
}
__global__ void fill_kernel(const int* __restrict__ ej, const int* __restrict__ ei,
                            int* __restrict__ cursor, int* __restrict__ elist,
                            int* __restrict__ js, int* __restrict__ is, int E) {
    int e = blockIdx.x * blockDim.x + threadIdx.x;
    if (e < E) {
        int j = ej[e];
        int slot = atomicAdd(&cursor[j], 1);
        elist[slot] = e;
        js[slot] = j;
        is[slot] = ei[e];
    }
}

// ---------------------------------------------------------------------------
// fp32 SGEMM with FFMA2 inner product: C = act(A @ W + bias)
// ---------------------------------------------------------------------------
template<int BM, int BN, int BK, int TM, int TN, int ACT, int HASB>
__global__ void __launch_bounds__(256)
sgemm_kernel(const float* __restrict__ A, const float* __restrict__ W,
             const float* __restrict__ bias, float* __restrict__ C,
             int M, int N, int K)
{
    __shared__ float As[BK][BM];
    __shared__ float Ws[BK][BN];

    const int tid  = threadIdx.x;
    const int row0 = blockIdx.x * BM;
    const int col0 = blockIdx.y * BN;
    const int tx   = tid % (BN / TN);
    const int ty   = tid / (BN / TN);

    const int aRow = tid / (BK / 4);
    const int aCol = (tid % (BK / 4)) * 4;
    const int wRow = tid / (BN / 4);
    const int wCol = (tid % (BN / 4)) * 4;

    ull acc2[TM][TN / 2];
#pragma unroll
    for (int i = 0; i < TM; i++)
#pragma unroll
        for (int j = 0; j < TN / 2; j++) acc2[i][j] = 0ULL;

    for (int k0 = 0; k0 < K; k0 += BK) {
#pragma unroll
        for (int r = 0; r < BM; r += 256 / (BK / 4)) {
            int gr = row0 + aRow + r;
            float4 v = make_float4(0.f, 0.f, 0.f, 0.f);
            if (gr < M)
                v = *(const float4*)(A + (size_t)gr * K + k0 + aCol);
            As[aCol + 0][aRow + r] = v.x;
            As[aCol + 1][aRow + r] = v.y;
            As[aCol + 2][aRow + r] = v.z;
            As[aCol + 3][aRow + r] = v.w;
        }
#pragma unroll
        for (int r = 0; r < BK; r += 256 / (BN / 4)) {
            *(float4*)&Ws[wRow + r][wCol] =
                *(const float4*)(W + (size_t)(k0 + wRow + r) * N + col0 + wCol);
        }
        __syncthreads();

#pragma unroll
        for (int k = 0; k < BK; k++) {
            float am[TM], wn[TN];
#pragma unroll
            for (int i = 0; i < TM; i += 4)
                *(float4*)&am[i] = *(const float4*)&As[k][ty * TM + i];
#pragma unroll
            for (int j = 0; j < TN; j += 4)
                *(float4*)&wn[j] = *(const float4*)&Ws[k][tx * TN + j];
            ull wn2[TN / 2];
#pragma unroll
            for (int j = 0; j < TN / 2; j++) wn2[j] = pk(wn[2 * j], wn[2 * j + 1]);
#pragma unroll
            for (int i = 0; i < TM; i++) {
                ull a2 = pk(am[i], am[i]);
#pragma unroll
                for (int j = 0; j < TN / 2; j++)
                    fma2(acc2[i][j], a2, wn2[j]);
            }
        }
        __syncthreads();
    }

    float bv[TN];
#pragma unroll
    for (int j = 0; j < TN; j++)
        bv[j] = HASB ? bias[col0 + tx * TN + j] : 0.f;

#pragma unroll
    for (int i = 0; i < TM; i++) {
        int gr = row0 + ty * TM + i;
        if (gr >= M) continue;
#pragma unroll
        for (int j = 0; j < TN; j += 4) {
            float t[4];
            upk(acc2[i][j / 2],     t[0], t[1]);
            upk(acc2[i][j / 2 + 1], t[2], t[3]);
#pragma unroll
            for (int q = 0; q < 4; q++) {
                float v = t[q] + bv[j + q];
                if (ACT == 1) v = v / (1.f + expf(-v)) * SSC;  // ScaledSiLU
                t[q] = v;
            }
            *(float4*)(C + (size_t)gr * N + col0 + tx * TN + j) =
                make_float4(t[0], t[1], t[2], t[3]);
        }
    }
}

// ---------------------------------------------------------------------------
// Vectorized global reduction
// ---------------------------------------------------------------------------
__device__ __forceinline__ void red4(float* p, float4 v) {
    asm volatile("red.global.add.v4.f32 [%0], {%1,%2,%3,%4};"
                 :: "l"(p), "f"(v.x), "f"(v.y), "f"(v.z), "f"(v.w)
                 : "memory");
}

// ---------------------------------------------------------------------------
// Pass A (j-sorted): rbf cols 0..255 fused with d_vec scatter.
// ef staged as duplicated (v,v) ull; inner loop reads 2 k per LDS.128 bcast.
// W slice 64KB + ef 32KB -> 2 CTAs/SM.
// ---------------------------------------------------------------------------
__global__ void __launch_bounds__(256, 2)
edge_vec_kernel(const float* __restrict__ xh, const float* __restrict__ xd,
                const float* __restrict__ vec, const float* __restrict__ efeat,
                const float* __restrict__ We, const float* __restrict__ be,
                const float* __restrict__ ev,
                const int* __restrict__ js, const int* __restrict__ is,
                const int* __restrict__ elist,
                float* __restrict__ dvec, int E)
{
    __shared__ float Ws[64 * 256];            // 64 KB
    __shared__ ull efs_all[8][EBA * 64];      // 32 KB

    const int tid = threadIdx.x;

    for (int idx = tid; idx < 64 * 64; idx += 256) {
        int k = idx >> 6, c4 = idx & 63;
        *(float4*)&Ws[k * 256 + c4 * 4] =
            *(const float4*)(We + (size_t)k * THDIM + c4 * 4);
    }
    __syncthreads();

    const int warp = tid >> 5;
    const int q    = tid & 31;
    ull* efs = efs_all[warp];

    const float4 be0 = *(const float4*)(be + 4 * q);
    const float4 be1 = *(const float4*)(be + HDIM + 4 * q);
    const float sv = IS3 * ISH;

    const int nG = E / EBA;
    const int gw = blockIdx.x * 8 + warp;
    const int stride = gridDim.x * 8;

    for (int g = gw; g < nG; g += stride) {
        const int e0 = g * EBA;

        // stage ef rows (duplicated pairs for FFMA2)
#pragma unroll
        for (int s = 0; s < EBA; s++) {
            int e = elist[e0 + s];
            float2 v = *(const float2*)(efeat + (size_t)e * FDIM + 2 * q);
            efs[s * 64 + 2 * q]     = pk(v.x, v.x);
            efs[s * 64 + 2 * q + 1] = pk(v.y, v.y);
        }
        __syncwarp();

        ull acc[EBA][4];
#pragma unroll
        for (int s = 0; s < EBA; s++)
#pragma unroll
            for (int c = 0; c < 4; c++) acc[s][c] = 0ULL;

#pragma unroll 4
        for (int k2 = 0; k2 < 32; k2++) {
            const float* wr = Ws + (k2 * 2) * 256 + 4 * q;
            ulonglong2 wa0 = *(const ulonglong2*)(wr);
            ulonglong2 wa1 = *(const ulonglong2*)(wr + 128);
            ulonglong2 wb0 = *(const ulonglong2*)(wr + 256);
            ulonglong2 wb1 = *(const ulonglong2*)(wr + 384);
#pragma unroll
            for (int s = 0; s < EBA; s++) {
                ulonglong2 ef = *(const ulonglong2*)&efs[s * 64 + k2 * 2];
                fma2(acc[s][0], ef.x, wa0.x);
                fma2(acc[s][1], ef.x, wa0.y);
                fma2(acc[s][2], ef.x, wa1.x);
                fma2(acc[s][3], ef.x, wa1.y);
                fma2(acc[s][0], ef.y, wb0.x);
                fma2(acc[s][1], ef.y, wb0.y);
                fma2(acc[s][2], ef.y, wb1.x);
                fma2(acc[s][3], ef.y, wb1.y);
            }
        }

        // epilogue: j-runs -> L1-hot gathers; atomic d_vec scatter
#pragma unroll
        for (int s = 0; s < EBA; s++) {
            const int e = elist[e0 + s];
            const int j = js[e0 + s];
            const int i = is[e0 + s];

            float r0[4], r1[4];
            upk(acc[s][0], r0[0], r0[1]); upk(acc[s][1], r0[2], r0[3]);
            upk(acc[s][2], r1[0], r1[1]); upk(acc[s][3], r1[2], r1[3]);
            r0[0] += be0.x; r0[1] += be0.y; r0[2] += be0.z; r0[3] += be0.w;
            r1[0] += be1.x; r1[1] += be1.y; r1[2] += be1.z; r1[3] += be1.w;

            const float4* xhj = (const float4*)(xh + (size_t)j * THDIM);
            const float4* xdj = (const float4*)(xd + (size_t)j * THDIM);
            const float4* xdi = (const float4*)(xd + (size_t)i * THDIM);
            const float4* vj  = (const float4*)(vec + (size_t)j * THDIM);

            float4 a0 = xhj[q],  a1 = xhj[32 + q];
            float4 b0 = xdj[q],  b1 = xdj[32 + q];
            float4 c0 = xdi[q],  c1 = xdi[32 + q];
            float4 v0 = vj[q],   v1 = vj[32 + q], v2 = vj[64 + q];

            float evd0 = ev[(size_t)e * 3 + 0];
            float evd1 = ev[(size_t)e * 3 + 1];
            float evd2 = ev[(size_t)e * 3 + 2];

            float4 m0, m1;
            m0.x = a0.x * (b0.x + c0.x) * r0[0] * sv;
            m0.y = a0.y * (b0.y + c0.y) * r0[1] * sv;
            m0.z = a0.z * (b0.z + c0.z) * r0[2] * sv;
            m0.w = a0.w * (b0.w + c0.w) * r0[3] * sv;
            m1.x = a1.x * (b1.x + c1.x) * r1[0] * sv;
            m1.y = a1.y * (b1.y + c1.y) * r1[1] * sv;
            m1.z = a1.z * (b1.z + c1.z) * r1[2] * sv;
            m1.w = a1.w * (b1.w + c1.w) * r1[3] * sv;

            float* dvb = dvec + (size_t)i * THDIM + 4 * q;
            float4 t;
            t.x = m0.x * v0.x + m1.x * evd0;
            t.y = m0.y * v0.y + m1.y * evd0;
            t.z = m0.z * v0.z + m1.z * evd0;
            t.w = m0.w * v0.w + m1.w * evd0;
            red4(dvb, t);
            t.x = m0.x * v1.x + m1.x * evd1;
            t.y = m0.y * v1.y + m1.y * evd1;
            t.z = m0.z * v1.z + m1.z * evd1;
            t.w = m0.w * v1.w + m1.w * evd1;
            red4(dvb + HDIM, t);
            t.x = m0.x * v2.x + m1.x * evd2;
            t.y = m0.y * v2.y + m1.y * evd2;
            t.z = m0.z * v2.z + m1.z * evd2;
            t.w = m0.w * v2.w + m1.w * evd2;
            red4(dvb + 2 * HDIM, t);
        }
        __syncwarp();
    }
}

// ---------------------------------------------------------------------------
// Pass B (j-sorted): rbf cols 256..383 fused with d_x scatter.
// ef staged plain float, 4 k per LDS.128 bcast + pk. 48KB -> 4 CTAs/SM.
// ---------------------------------------------------------------------------
__global__ void __launch_bounds__(256, 4)
edge_dx_kernel(const float* __restrict__ xh, const float* __restrict__ xd,
               const float* __restrict__ efeat,
               const float* __restrict__ We, const float* __restrict__ be,
               const int* __restrict__ js, const int* __restrict__ is,
               const int* __restrict__ elist,
               float* __restrict__ dx, int E)
{
    __shared__ float Ws[64 * 128];            // 32 KB
    __shared__ float efs_all[8][EBA * 64];    // 16 KB

    const int tid = threadIdx.x;

    for (int idx = tid; idx < 64 * 32; idx += 256) {
        int k = idx >> 5, c4 = idx & 31;
        *(float4*)&Ws[k * 128 + c4 * 4] =
            *(const float4*)(We + (size_t)k * THDIM + 256 + c4 * 4);
    }
    __syncthreads();

    const int warp = tid >> 5;
    const int q    = tid & 31;
    float* efs = efs_all[warp];

    const float4 be2 = *(const float4*)(be + 2 * HDIM + 4 * q);

    const int nG = E / EBA;
    const int gw = blockIdx.x * 8 + warp;
    const int stride = gridDim.x * 8;

    for (int g = gw; g < nG; g += stride) {
        const int e0 = g * EBA;

#pragma unroll
        for (int s = 0; s < EBA; s++) {
            int e = elist[e0 + s];
            float2 v = *(const float2*)(efeat + (size_t)e * FDIM + 2 * q);
            efs[s * 64 + 2 * q]     = v.x;
            efs[s * 64 + 2 * q + 1] = v.y;
        }
        __syncwarp();

        ull acc[EBA][2];
#pragma unroll
        for (int s = 0; s < EBA; s++) { acc[s][0] = 0ULL; acc[s][1] = 0ULL; }

#pragma unroll 2
        for (int k4 = 0; k4 < 16; k4++) {
            const float* wr = Ws + (k4 * 4) * 128 + 4 * q;
            ulonglong2 w0 = *(const ulonglong2*)(wr);
            ulonglong2 w1 = *(const ulonglong2*)(wr + 128);
            ulonglong2 w2 = *(const ulonglong2*)(wr + 256);
            ulonglong2 w3 = *(const ulonglong2*)(wr + 384);
#pragma unroll
            for (int s = 0; s < EBA; s++) {
                float4 efv = *(const float4*)&efs[s * 64 + k4 * 4];
                ull ea = pk(efv.x, efv.x), eb = pk(efv.y, efv.y);
                ull ec = pk(efv.z, efv.z), ed = pk(efv.w, efv.w);
                fma2(acc[s][0], ea, w0.x); fma2(acc[s][1], ea, w0.y);
                fma2(acc[s][0], eb, w1.x); fma2(acc[s][1], eb, w1.y);
                fma2(acc[s][0], ec, w2.x); fma2(acc[s][1], ec, w2.y);
                fma2(acc[s][0], ed, w3.x); fma2(acc[s][1], ed, w3.y);
            }
        }

#pragma unroll
        for (int s = 0; s < EBA; s++) {
            const int j = js[e0 + s];
            const int i = is[e0 + s];

            float r2[4];
            upk(acc[s][0], r2[0], r2[1]); upk(acc[s][1], r2[2], r2[3]);
            r2[0] += be2.x; r2[1] += be2.y; r2[2] += be2.z; r2[3] += be2.w;

            const float4* xhj = (const float4*)(xh + (size_t)j * THDIM);
            const float4* xdj = (const float4*)(xd + (size_t)j * THDIM);
            const float4* xdi = (const float4*)(xd + (size_t)i * THDIM);

            float4 a = xhj[64 + q], b = xdj[64 + q], c = xdi[64 + q];
            float4 m;
            m.x = a.x * (b.x + c.x) * r2[0] * IS3;
            m.y = a.y * (b.y + c.y) * r2[1] * IS3;
            m.z = a.z * (b.z + c.z) * r2[2] * IS3;
            m.w = a.w * (b.w + c.w) * r2[3] * IS3;

            red4(dx + (size_t)i * HDIM + 4 * q, m);
        }
        __syncwarp();
    }
}

// ---------------------------------------------------------------------------
// Vector activation epilogue
// ---------------------------------------------------------------------------
__global__ void combine_kernel(const float* __restrict__ lvec,
                               const float* __restrict__ Wg,
                               float* __restrict__ dvec, int Nn)
{
    __shared__ float wg_s[HDIM];
    __shared__ float red_s[4][3];
    int t = threadIdx.x;   // 128
    wg_s[t] = Wg[t];
    __syncthreads();

    for (int n = blockIdx.x; n < Nn; n += gridDim.x) {
        const float* vr = dvec + (size_t)n * THDIM;
        float v0 = vr[t], v1 = vr[HDIM + t], v2 = vr[2 * HDIM + t];
        float w = wg_s[t];
        float p0 = v0 * w, p1 = v1 * w, p2 = v2 * w;
#pragma unroll
        for (int off = 16; off > 0; off >>= 1) {
            p0 += __shfl_xor_sync(0xffffffffu, p0, off);
            p1 += __shfl_xor_sync(0xffffffffu, p1, off);
            p2 += __shfl_xor_sync(0xffffffffu, p2, off);
        }
        if ((t & 31) == 0) {
            red_s[t >> 5][0] = p0;
            red_s[t >> 5][1] = p1;
            red_s[t >> 5][2] = p2;
        }
        __syncthreads();
        float gv0 = red_s[0][0] + red_s[1][0] + red_s[2][0] + red_s[3][0];
        float gv1 = red_s[0][1] + red_s[1][1] + red_s[2][1] + red_s[3][1];
        float gv2 = red_s[0][2] + red_s[1][2] + red_s[2][2] + red_s[3][2];

        const float* lv = lvec + (size_t)n * THDIM;
        float l0 = lv[t], l1 = lv[HDIM + t], l2 = lv[2 * HDIM + t];
        float dot = l0 * gv0 + l1 * gv1 + l2 * gv2;

        float* o = dvec + (size_t)n * THDIM;
        if (dot >= 0.f) {
            o[t] = l0; o[HDIM + t] = l1; o[2 * HDIM + t] = l2;
        } else {
            o[t]            = (l0 + gv0) * 0.5f;
            o[HDIM + t]     = (l1 + gv1) * 0.5f;
            o[2 * HDIM + t] = (l2 + gv2) * 0.5f;
        }
        __syncthreads();
    }
}

// ---------------------------------------------------------------------------
// Launch: forked-stream schedule (graph-capture-safe via event dependencies)
//   main stream: zero -> gemms ----\
//   side stream: CSR build --------- join -> edge_vec -> lvec -> combine
//                        \-> edge_dx (on side stream, overlaps lvec/combine)
// ---------------------------------------------------------------------------
extern "C" void kernel_launch(void* const* d_in, const int* in_sizes, int n_in,
                              void* d_out, int out_size)
{
    const float* x     = (const float*)d_in[0];
    const float* xdef  = (const float*)d_in[1];
    const float* vec   = (const float*)d_in[2];
    const float* efeat = (const float*)d_in[3];
    const float* evec  = (const float*)d_in[4];
    const int*   eidx  = (const int*)  d_in[5];
    const float* Wd    = (const float*)d_in[6];
    const float* bd    = (const float*)d_in[7];
    const float* W1    = (const float*)d_in[8];
    const float* b1    = (const float*)d_in[9];
    const float* W2    = (const float*)d_in[10];
    const float* b2    = (const float*)d_in[11];
    const float* We    = (const float*)d_in[12];
    const float* be    = (const float*)d_in[13];
    const float* Wl    = (const float*)d_in[14];
    const float* Wg    = (const float*)d_in[15];

    int N = in_sizes[0] / HDIM;     // 50000
    int E = in_sizes[4] / 3;        // 400000

    float *p_xd, *p_h1, *p_xh, *p_lvec;
    int *p_deg, *p_cur, *p_bsum, *p_boff, *p_elist, *p_js, *p_is;
    cudaGetSymbolAddress((void**)&p_xd,    g_xd);
    cudaGetSymbolAddress((void**)&p_h1,    g_h1);
    cudaGetSymbolAddress((void**)&p_xh,    g_xh);
    cudaGetSymbolAddress((void**)&p_lvec,  g_lvec);
    cudaGetSymbolAddress((void**)&p_deg,   g_deg);
    cudaGetSymbolAddress((void**)&p_cur,   g_cur);
    cudaGetSymbolAddress((void**)&p_bsum,  g_bsum);
    cudaGetSymbolAddress((void**)&p_boff,  g_boff);
    cudaGetSymbolAddress((void**)&p_elist, g_elist);
    cudaGetSymbolAddress((void**)&p_js,    g_js);
    cudaGetSymbolAddress((void**)&p_is,    g_is);

    float* dx   = (float*)d_out;
    float* dvec = (float*)d_out + (size_t)N * HDIM;

    const int* ej = eidx;
    const int* ei = eidx + E;

    cudaStream_t s0 = 0;   // legacy default stream (capture origin)
    cudaStream_t sB;
    cudaStreamCreateWithFlags(&sB, cudaStreamNonBlocking);
    cudaEvent_t evFork, evCSR, evJoin, evB;
    cudaEventCreateWithFlags(&evFork, cudaEventDisableTiming);
    cudaEventCreateWithFlags(&evCSR,  cudaEventDisableTiming);
    cudaEventCreateWithFlags(&evJoin, cudaEventDisableTiming);
    cudaEventCreateWithFlags(&evB,    cudaEventDisableTiming);

    // ---- fork 1: CSR build on sB, zero+GEMMs on main -----------------------
    cudaEventRecord(evFork, s0);
    cudaStreamWaitEvent(sB, evFork, 0);

    int nb = (N + 255) / 256;
    zeroi_kernel<<<(N + 255) / 256, 256, 0, sB>>>(p_deg, N);
    hist_kernel<<<(E + 255) / 256, 256, 0, sB>>>(ej, p_deg, E);
    scan1_kernel<<<nb, 256, 0, sB>>>(p_deg, p_bsum, N);
    scan2_kernel<<<1, 256, 0, sB>>>(p_bsum, p_boff, nb);
    scan3_kernel<<<nb, 256, 0, sB>>>(p_deg, p_boff, p_cur, N);
    fill_kernel<<<(E + 255) / 256, 256, 0, sB>>>(ej, ei, p_cur, p_elist,
                                                 p_js, p_is, E);
    cudaEventRecord(evCSR, sB);

    long n4 = (long)out_size / 4;
    zero_kernel<<<(unsigned)((n4 + 255) / 256), 256, 0, s0>>>((float4*)d_out, n4);

    dim3 gN((N + 127) / 128, 3);
    dim3 gN1((N + 127) / 128, 1);
    dim3 gL((3 * N + 127) / 128, 1);

    sgemm_kernel<128,128,16,8,8,0,1><<<gN, 256, 0, s0>>>(xdef, Wd, bd, p_xd, N, THDIM, HDIM);
    sgemm_kernel<128, 64,16,8,4,1,1><<<gN1,256, 0, s0>>>(x, W1, b1, p_h1, N, FDIM, HDIM);
    sgemm_kernel<128,128,16,8,8,0,1><<<gN, 256, 0, s0>>>(p_h1, W2, b2, p_xh, N, THDIM, FDIM);

    // join CSR into main before edge passes
    cudaStreamWaitEvent(s0, evCSR, 0);

    // ---- fork 2: edge_dx on sB (overlaps edge_vec + lvec + combine) --------
    cudaEventRecord(evJoin, s0);
    cudaStreamWaitEvent(sB, evJoin, 0);
    edge_dx_kernel<<<592, 256, 0, sB>>>(p_xh, p_xd, efeat, We, be,
                                        p_js, p_is, p_elist, dx, E);
    cudaEventRecord(evB, sB);

    // main: pass A -> lvec -> combine
    edge_vec_kernel<<<296, 256, 0, s0>>>(p_xh, p_xd, vec, efeat, We, be, evec,
                                         p_js, p_is, p_elist, dvec, E);
    sgemm_kernel<128,128,16,8,8,0,0><<<gL, 256, 0, s0>>>(dvec, Wl, nullptr,
                                                          p_lvec, 3 * N, HDIM, HDIM);
    combine_kernel<<<2048, 128, 0, s0>>>(p_lvec, Wg, dvec, N);

    // ---- join pass B back into main ----------------------------------------
    cudaStreamWaitEvent(s0, evB, 0);

    cudaEventDestroy(evFork);
    cudaEventDestroy(evCSR);
    cudaEventDestroy(evJoin);
    cudaEventDestroy(evB);
    cudaStreamDestroy(sB);
}